// round 10
// baseline (speedup 1.0000x reference)
#include <cuda_runtime.h>
#include <cuda_bf16.h>
#include <cstdint>

// out[i] = softmax((x2[i] @ v1^T)/1000) @ x2[i],  v1 = x1@W.T + b,  N=384.
// P = 1/384 + delta  ->  out = colsum(x2[i])/384 + delta @ x2[i].
// GEMMs: mma.sync m16n8k16 bf16, prebaked bf16 operands.
// Attn: 128-row CTA tiles, 512 threads (16 warps = 4x4), K=32 chunks (12 iters/GEMM).

constexpr int N = 384;
constexpr float SCALE_INV = 1.0f / 1000.0f;
constexpr float INV_N = 1.0f / 384.0f;

constexpr int QS  = 392;   // sQ row stride (halves): 384 + 8 pad
constexpr int BS2 = 40;    // GEMM1 B row stride (halves): 32 data + 8 pad
constexpr int VS  = 392;   // GEMM2 B row stride (halves)

constexpr int SQ_BYTES = 128 * QS * 2;        // 100352
constexpr int BUF_B    = 30720;               // max(384*BS2*2, 32*VS*2) = max(30720, 25088)
constexpr int OFF_BUF  = SQ_BYTES;
constexpr int OFF_SROW = OFF_BUF + 3 * BUF_B;            // 192512
constexpr int OFF_CS   = OFF_SROW + 512 * 4;             // 194560
constexpr int SMEM_ATTN = OFF_CS + 384 * 4;              // 196096

__device__ __align__(16) __nv_bfloat16 g_v1b[N * N];                 // v1[n][k] bf16
__device__ __align__(16) __nv_bfloat16 g_x2b[(size_t)N * N * N];     // x2 bf16 image
__device__ float g_cs6[(size_t)N * 6 * N];                           // partial colsums

// ---------------------------------------------------------------------------
__device__ __forceinline__ uint32_t smem_u32(const void* p) {
    uint32_t a;
    asm("{ .reg .u64 t; cvta.to.shared.u64 t, %1; cvt.u32.u64 %0, t; }" : "=r"(a) : "l"(p));
    return a;
}
__device__ __forceinline__ void ldm4(uint32_t* r, uint32_t addr) {
    asm volatile("ldmatrix.sync.aligned.m8n8.x4.shared.b16 {%0,%1,%2,%3},[%4];"
                 : "=r"(r[0]), "=r"(r[1]), "=r"(r[2]), "=r"(r[3]) : "r"(addr));
}
__device__ __forceinline__ void ldm4t(uint32_t* r, uint32_t addr) {
    asm volatile("ldmatrix.sync.aligned.m8n8.x4.trans.shared.b16 {%0,%1,%2,%3},[%4];"
                 : "=r"(r[0]), "=r"(r[1]), "=r"(r[2]), "=r"(r[3]) : "r"(addr));
}
__device__ __forceinline__ void mma16816(float* d, const uint32_t* a, uint32_t b0, uint32_t b1) {
    asm volatile("mma.sync.aligned.m16n8k16.row.col.f32.bf16.bf16.f32 "
                 "{%0,%1,%2,%3},{%4,%5,%6,%7},{%8,%9},{%0,%1,%2,%3};"
                 : "+f"(d[0]), "+f"(d[1]), "+f"(d[2]), "+f"(d[3])
                 : "r"(a[0]), "r"(a[1]), "r"(a[2]), "r"(a[3]), "r"(b0), "r"(b1));
}
__device__ __forceinline__ uint32_t bf2_pack(float a, float b) {
    __nv_bfloat162 h = __floats2bfloat162_rn(a, b);
    return *reinterpret_cast<uint32_t*>(&h);
}
__device__ __forceinline__ void cp16(uint32_t dst, const void* src) {
    asm volatile("cp.async.cg.shared.global [%0], [%1], 16;" :: "r"(dst), "l"(src));
}
#define CP_COMMIT() asm volatile("cp.async.commit_group;" ::: "memory")
#define CP_WAIT1()  asm volatile("cp.async.wait_group 1;" ::: "memory")

// ---------------------------------------------------------------------------
// prep kernel, grid (6, 386): by<2 -> linear slab; by>=2 -> x2 bf16 + colsum
// ---------------------------------------------------------------------------
constexpr int SMEM_PREP = (32 * 17 + 384 * 17) * 4;   // 28288

__global__ __launch_bounds__(256) void prep_kernel(const float* __restrict__ x1,
                                                   const float* __restrict__ W,
                                                   const float* __restrict__ b,
                                                   const float* __restrict__ x2) {
    extern __shared__ float dsf[];
    const int tid = threadIdx.x;
    const int bx = blockIdx.x, by = blockIdx.y;

    if (by < 2) {
        float* sX = dsf;                // [32][17]
        float* sW = dsf + 32 * 17;      // [384][17]
        const int L = by * 6 + bx;
        const int n0 = L * 32;
        const int nl = (tid & 15) * 2;
        const int k0 = (tid >> 4) * 24;
        float acc[2][24];
#pragma unroll
        for (int r = 0; r < 2; ++r)
#pragma unroll
            for (int j = 0; j < 24; ++j) acc[r][j] = 0.0f;

        for (int m0 = 0; m0 < N; m0 += 16) {
#pragma unroll
            for (int q = 0; q < 2; ++q) {
                int idx = tid + q * 256;
                int n = idx >> 4, m = idx & 15;
                sX[n * 17 + m] = x1[(size_t)(n0 + n) * N + m0 + m];
            }
#pragma unroll
            for (int q = 0; q < 24; ++q) {
                int idx = tid + q * 256;
                int k = idx >> 4, m = idx & 15;
                sW[k * 17 + m] = W[(size_t)k * N + m0 + m];
            }
            __syncthreads();
#pragma unroll
            for (int mm = 0; mm < 16; ++mm) {
                float x0 = sX[nl * 17 + mm];
                float x1v = sX[(nl + 1) * 17 + mm];
#pragma unroll
                for (int j = 0; j < 24; ++j) {
                    float w = sW[(k0 + j) * 17 + mm];
                    acc[0][j] += x0 * w;
                    acc[1][j] += x1v * w;
                }
            }
            __syncthreads();
        }
#pragma unroll
        for (int r = 0; r < 2; ++r) {
            int n = n0 + nl + r;
            uint32_t* dst = reinterpret_cast<uint32_t*>(g_v1b + (size_t)n * N + k0);
#pragma unroll
            for (int j = 0; j < 12; ++j)
                dst[j] = bf2_pack(acc[r][2 * j] + __ldg(b + k0 + 2 * j),
                                  acc[r][2 * j + 1] + __ldg(b + k0 + 2 * j + 1));
        }
        return;
    }

    // direct x2 -> bf16 + register colsum (64-row slab)
    const int i = by - 2, s = bx;
    float4* red = reinterpret_cast<float4*>(dsf);   // [192] float4
    if (tid < 192) {
        const int c4 = tid % 96;
        const int rh = tid / 96;
        const float* src = x2 + ((size_t)i * N + s * 64) * N;
        __nv_bfloat16* dst = g_x2b + ((size_t)i * N + s * 64) * N;
        float4 sum = make_float4(0.f, 0.f, 0.f, 0.f);
#pragma unroll
        for (int q = 0; q < 32; ++q) {
            int r = rh + 2 * q;
            float4 f = __ldg(reinterpret_cast<const float4*>(src + (size_t)r * N) + c4);
            sum.x += f.x; sum.y += f.y; sum.z += f.z; sum.w += f.w;
            uint2 u = make_uint2(bf2_pack(f.x, f.y), bf2_pack(f.z, f.w));
            *reinterpret_cast<uint2*>(dst + (size_t)r * N + c4 * 4) = u;
        }
        red[tid] = sum;
    }
    __syncthreads();
    if (tid < 96) {
        float4 a = red[tid], c = red[tid + 96];
        a.x += c.x; a.y += c.y; a.z += c.z; a.w += c.w;
        *reinterpret_cast<float4*>(g_cs6 + ((size_t)i * 6 + s) * N + tid * 4) = a;
    }
}

// ---------------------------------------------------------------------------
// Fused attention: 512 threads, 16 warps = 4 row x 4 col groups, K=32 chunks.
// ---------------------------------------------------------------------------
__global__ __launch_bounds__(512, 1)
void attn_kernel(float* __restrict__ out) {
    extern __shared__ char smem[];
    __nv_bfloat16* sQ = reinterpret_cast<__nv_bfloat16*>(smem);
    float* srow = reinterpret_cast<float*>(smem + OFF_SROW);   // [4 wc][128 rows]
    float* cs_s = reinterpret_cast<float*>(smem + OFF_CS);

    const int tid = threadIdx.x;
    const int lane = tid & 31;
    const int warp = tid >> 5;
    const int wr = warp & 3;       // rows wr*32..+32
    const int wc = warp >> 2;      // cols wc*96..+96
    const int i = blockIdx.y;
    const int j0 = blockIdx.x * 128;

    const uint32_t sQu = smem_u32(smem);
    const uint32_t sBu = sQu + OFF_BUF;

    const int rowA = (lane & 7) + ((lane >> 3) & 1) * 8;
    const int colA = (lane >> 4) * 8;
    const uint32_t aBase = sQu + ((wr * 32 + rowA) * QS + colA) * 2;

    const int rowB = (lane & 7) + ((lane >> 4) & 1) * 8;
    const int colB = ((lane >> 3) & 1) * 8;
    const uint32_t bBase1 = sBu + (rowB * BS2 + colB) * 2;

    const int rowV = (lane & 7) + ((lane >> 3) & 1) * 8;
    const int colV = ((lane >> 4) & 1) * 8;
    const uint32_t bBase2 = sBu + (rowV * VS + colV) * 2;

    // ---- stage Q (128x384 bf16 = 6144 x 16B) + v1 chunks 0,1 (K=32 each) ----
    const char* qsrc = reinterpret_cast<const char*>(g_x2b + ((size_t)i * N + j0) * N);
#pragma unroll
    for (int q = 0; q < 12; ++q) {
        int idx = tid + q * 512;
        int row = idx / 48, c = idx % 48;
        cp16(sQu + row * 784 + c * 16, qsrc + (size_t)idx * 16);
    }
    const char* v1src = reinterpret_cast<const char*>(g_v1b);
#pragma unroll
    for (int q = 0; q < 3; ++q) {          // chunk 0 -> buf0 (1536 x 16B)
        int idx = tid + q * 512;
        int n = idx >> 2, h = idx & 3;
        cp16(sBu + n * 80 + h * 16, v1src + (size_t)n * 768 + h * 16);
    }
    CP_COMMIT();
#pragma unroll
    for (int q = 0; q < 3; ++q) {          // chunk 1 -> buf1
        int idx = tid + q * 512;
        int n = idx >> 2, h = idx & 3;
        cp16(sBu + BUF_B + n * 80 + h * 16, v1src + (size_t)n * 768 + 64 + h * 16);
    }
    CP_COMMIT();

    float acc[2][12][4];
#pragma unroll
    for (int ma = 0; ma < 2; ++ma)
#pragma unroll
        for (int na = 0; na < 12; ++na)
#pragma unroll
            for (int r = 0; r < 4; ++r) acc[ma][na][r] = 0.0f;

    // =================== GEMM1: S = Q @ v1^T (12 chunks of K=32) ===================
    for (int kc = 0; kc < 12; ++kc) {
        const int buf = kc % 3;
        CP_WAIT1();
        __syncthreads();
        if (kc + 2 < 12) {
            const int nb = (kc + 2) % 3;
#pragma unroll
            for (int q = 0; q < 3; ++q) {
                int idx = tid + q * 512;
                int n = idx >> 2, h = idx & 3;
                cp16(sBu + nb * BUF_B + n * 80 + h * 16,
                     v1src + (size_t)n * 768 + (kc + 2) * 64 + h * 16);
            }
        }
        CP_COMMIT();
#pragma unroll
        for (int kk = 0; kk < 2; ++kk) {
            uint32_t a[2][4];
#pragma unroll
            for (int ma = 0; ma < 2; ++ma)
                ldm4(a[ma], aBase + (ma * 16 * QS + (kc * 32 + kk * 16)) * 2);
#pragma unroll
            for (int nbx = 0; nbx < 6; ++nbx) {
                uint32_t bfr[4];
                ldm4(bfr, bBase1 + buf * BUF_B + (wc * 96 + nbx * 16) * 80 + kk * 32);
#pragma unroll
                for (int ma = 0; ma < 2; ++ma) {
                    mma16816(acc[ma][2 * nbx], a[ma], bfr[0], bfr[1]);
                    mma16816(acc[ma][2 * nbx + 1], a[ma], bfr[2], bfr[3]);
                }
            }
        }
    }

    // ---- prefetch V chunks 0,1 (32 rows each; overlap with softmax) ----
    const char* vsrc = reinterpret_cast<const char*>(g_x2b + (size_t)i * N * N);
#pragma unroll
    for (int q = 0; q < 3; ++q) {
        int idx = tid + q * 512;
        int row = idx / 48, c = idx % 48;
        cp16(sBu + row * 784 + c * 16, vsrc + (size_t)idx * 16);
    }
    CP_COMMIT();
#pragma unroll
    for (int q = 0; q < 3; ++q) {
        int idx = tid + q * 512;
        int row = idx / 48, c = idx % 48;
        cp16(sBu + BUF_B + row * 784 + c * 16, vsrc + 24576 + (size_t)idx * 16);
    }
    CP_COMMIT();

    // ---- colsum -> smem ----
    if (tid < 384) {
        float s0 = 0.f;
#pragma unroll
        for (int p = 0; p < 6; ++p) s0 += __ldg(g_cs6 + ((size_t)i * 6 + p) * N + tid);
        cs_s[tid] = s0;
    }

    // =================== softmax: delta = e/s - 1/N (bf16 into sQ) ===================
    float rs[2][2] = {{0.f, 0.f}, {0.f, 0.f}};
#pragma unroll
    for (int ma = 0; ma < 2; ++ma)
#pragma unroll
        for (int na = 0; na < 12; ++na) {
            float* d = acc[ma][na];
            d[0] = __expf(d[0] * SCALE_INV);
            d[1] = __expf(d[1] * SCALE_INV);
            d[2] = __expf(d[2] * SCALE_INV);
            d[3] = __expf(d[3] * SCALE_INV);
            rs[ma][0] += d[0] + d[1];
            rs[ma][1] += d[2] + d[3];
        }
#pragma unroll
    for (int ma = 0; ma < 2; ++ma)
#pragma unroll
        for (int h = 0; h < 2; ++h) {
            rs[ma][h] += __shfl_xor_sync(0xffffffffu, rs[ma][h], 1);
            rs[ma][h] += __shfl_xor_sync(0xffffffffu, rs[ma][h], 2);
        }
    if ((lane & 3) == 0) {
#pragma unroll
        for (int ma = 0; ma < 2; ++ma)
#pragma unroll
            for (int h = 0; h < 2; ++h)
                srow[wc * 128 + wr * 32 + ma * 16 + h * 8 + (lane >> 2)] = rs[ma][h];
    }
    __syncthreads();
    float invs[2][2];
#pragma unroll
    for (int ma = 0; ma < 2; ++ma)
#pragma unroll
        for (int h = 0; h < 2; ++h) {
            int r = wr * 32 + ma * 16 + h * 8 + (lane >> 2);
            invs[ma][h] = 1.0f / (srow[r] + srow[128 + r] + srow[256 + r] + srow[384 + r]);
        }
#pragma unroll
    for (int ma = 0; ma < 2; ++ma)
#pragma unroll
        for (int na = 0; na < 12; ++na) {
            int r = wr * 32 + ma * 16 + (lane >> 2);
            int c = wc * 96 + (na >> 1) * 16 + (na & 1) * 8 + (lane & 3) * 2;
            float* d = acc[ma][na];
            *reinterpret_cast<uint32_t*>(sQ + r * QS + c) =
                bf2_pack(d[0] * invs[ma][0] - INV_N, d[1] * invs[ma][0] - INV_N);
            *reinterpret_cast<uint32_t*>(sQ + (r + 8) * QS + c) =
                bf2_pack(d[2] * invs[ma][1] - INV_N, d[3] * invs[ma][1] - INV_N);
        }
    __syncthreads();

    // =================== GEMM2: corr = delta @ V (12 chunks of 32 rows) ===================
#pragma unroll
    for (int ma = 0; ma < 2; ++ma)
#pragma unroll
        for (int na = 0; na < 12; ++na)
#pragma unroll
            for (int r = 0; r < 4; ++r) acc[ma][na][r] = 0.0f;

    for (int nc = 0; nc < 12; ++nc) {
        const int buf = nc % 3;
        CP_WAIT1();
        __syncthreads();
        if (nc + 2 < 12) {
            const int nb = (nc + 2) % 3;
#pragma unroll
            for (int q = 0; q < 3; ++q) {
                int idx = tid + q * 512;
                int row = idx / 48, c = idx % 48;
                cp16(sBu + nb * BUF_B + row * 784 + c * 16,
                     vsrc + (size_t)(nc + 2) * 24576 + (size_t)idx * 16);
            }
        }
        CP_COMMIT();
#pragma unroll
        for (int kk = 0; kk < 2; ++kk) {
            uint32_t a[2][4];
#pragma unroll
            for (int ma = 0; ma < 2; ++ma)
                ldm4(a[ma], aBase + (ma * 16 * QS + (nc * 32 + kk * 16)) * 2);
#pragma unroll
            for (int nbx = 0; nbx < 6; ++nbx) {
                uint32_t bfr[4];
                ldm4t(bfr, bBase2 + buf * BUF_B + kk * 12544 + (wc * 96 + nbx * 16) * 2);
#pragma unroll
                for (int ma = 0; ma < 2; ++ma) {
                    mma16816(acc[ma][2 * nbx], a[ma], bfr[0], bfr[1]);
                    mma16816(acc[ma][2 * nbx + 1], a[ma], bfr[2], bfr[3]);
                }
            }
        }
    }

    // =================== epilogue: out = corr + colsum/384 ===================
#pragma unroll
    for (int ma = 0; ma < 2; ++ma)
#pragma unroll
        for (int nbx = 0; nbx < 6; ++nbx)
#pragma unroll
            for (int ct = 0; ct < 2; ++ct) {
                int na = nbx * 2 + ct;
                int r = j0 + wr * 32 + ma * 16 + (lane >> 2);
                int c = wc * 96 + nbx * 16 + ct * 8 + (lane & 3) * 2;
                float cs0 = cs_s[c] * INV_N;
                float cs1 = cs_s[c + 1] * INV_N;
                float* d = acc[ma][na];
                float2 o0 = make_float2(d[0] + cs0, d[1] + cs1);
                float2 o1 = make_float2(d[2] + cs0, d[3] + cs1);
                *reinterpret_cast<float2*>(out + ((size_t)i * N + r) * N + c) = o0;
                *reinterpret_cast<float2*>(out + ((size_t)i * N + r + 8) * N + c) = o1;
            }
}

// ---------------------------------------------------------------------------
extern "C" void kernel_launch(void* const* d_in, const int* in_sizes, int n_in,
                              void* d_out, int out_size) {
    const float* x1 = (const float*)d_in[0];
    const float* x2 = (const float*)d_in[1];
    const float* W  = (const float*)d_in[2];
    const float* b  = (const float*)d_in[3];
    float* out = (float*)d_out;
    (void)in_sizes; (void)n_in; (void)out_size;

    {
        cudaFuncSetAttribute(prep_kernel, cudaFuncAttributeMaxDynamicSharedMemorySize, SMEM_PREP);
        dim3 g(6, 386);
        prep_kernel<<<g, 256, SMEM_PREP>>>(x1, W, b, x2);
    }
    {
        cudaFuncSetAttribute(attn_kernel, cudaFuncAttributeMaxDynamicSharedMemorySize, SMEM_ATTN);
        dim3 g(3, 384);
        attn_kernel<<<g, 512, SMEM_ATTN>>>(out);
    }
}

// round 11
// speedup vs baseline: 1.9265x; 1.9265x over previous
#include <cuda_runtime.h>
#include <cuda_bf16.h>
#include <cstdint>

// out[i] = softmax((x2[i] @ v1^T)/1000) @ x2[i],  v1 = x1@W.T + b,  N=384.
// P = 1/384 + delta  ->  out = colsum(x2[i])/384 + delta @ x2[i].
// GEMMs: mma.sync m16n8k16 bf16, prebaked bf16 operands.
// Attn: R8 configuration (best known): 128-row tiles, 512 thr, K=16 chunks.
// Prep: R9 direct register-resident convert + colsum (cheaper than R8 prep).

constexpr int N = 384;
constexpr float SCALE_INV = 1.0f / 1000.0f;
constexpr float INV_N = 1.0f / 384.0f;

constexpr int QS = 392;   // sQ row stride (halves): 384 + 8 pad
constexpr int BS = 24;    // GEMM1 B row stride (halves): 16 + 8 pad
constexpr int VS = 392;   // GEMM2 B row stride (halves)

constexpr int SQ_BYTES = 128 * QS * 2;        // 100352
constexpr int BUF_B    = 18432;               // max(384*BS*2, 16*VS*2)
constexpr int OFF_BUF  = SQ_BYTES;
constexpr int OFF_SROW = OFF_BUF + 3 * BUF_B;            // 155648
constexpr int OFF_CS   = OFF_SROW + 512 * 4;             // 157696
constexpr int SMEM_ATTN = OFF_CS + 384 * 4;              // 159232

__device__ __align__(16) __nv_bfloat16 g_v1b[N * N];                 // v1[n][k] bf16
__device__ __align__(16) __nv_bfloat16 g_x2b[(size_t)N * N * N];     // x2 bf16 image
__device__ float g_cs6[(size_t)N * 6 * N];                           // partial colsums

// ---------------------------------------------------------------------------
__device__ __forceinline__ uint32_t smem_u32(const void* p) {
    uint32_t a;
    asm("{ .reg .u64 t; cvta.to.shared.u64 t, %1; cvt.u32.u64 %0, t; }" : "=r"(a) : "l"(p));
    return a;
}
__device__ __forceinline__ void ldm4(uint32_t* r, uint32_t addr) {
    asm volatile("ldmatrix.sync.aligned.m8n8.x4.shared.b16 {%0,%1,%2,%3},[%4];"
                 : "=r"(r[0]), "=r"(r[1]), "=r"(r[2]), "=r"(r[3]) : "r"(addr));
}
__device__ __forceinline__ void ldm4t(uint32_t* r, uint32_t addr) {
    asm volatile("ldmatrix.sync.aligned.m8n8.x4.trans.shared.b16 {%0,%1,%2,%3},[%4];"
                 : "=r"(r[0]), "=r"(r[1]), "=r"(r[2]), "=r"(r[3]) : "r"(addr));
}
__device__ __forceinline__ void mma16816(float* d, const uint32_t* a, uint32_t b0, uint32_t b1) {
    asm volatile("mma.sync.aligned.m16n8k16.row.col.f32.bf16.bf16.f32 "
                 "{%0,%1,%2,%3},{%4,%5,%6,%7},{%8,%9},{%0,%1,%2,%3};"
                 : "+f"(d[0]), "+f"(d[1]), "+f"(d[2]), "+f"(d[3])
                 : "r"(a[0]), "r"(a[1]), "r"(a[2]), "r"(a[3]), "r"(b0), "r"(b1));
}
__device__ __forceinline__ uint32_t bf2_pack(float a, float b) {
    __nv_bfloat162 h = __floats2bfloat162_rn(a, b);
    return *reinterpret_cast<uint32_t*>(&h);
}
__device__ __forceinline__ void cp16(uint32_t dst, const void* src) {
    asm volatile("cp.async.cg.shared.global [%0], [%1], 16;" :: "r"(dst), "l"(src));
}
#define CP_COMMIT() asm volatile("cp.async.commit_group;" ::: "memory")
#define CP_WAIT1()  asm volatile("cp.async.wait_group 1;" ::: "memory")

// ---------------------------------------------------------------------------
// prep kernel, grid (6, 386): by<2 -> linear slab; by>=2 -> x2 bf16 + colsum
// ---------------------------------------------------------------------------
constexpr int SMEM_PREP = (32 * 17 + 384 * 17) * 4;   // 28288

__global__ __launch_bounds__(256) void prep_kernel(const float* __restrict__ x1,
                                                   const float* __restrict__ W,
                                                   const float* __restrict__ b,
                                                   const float* __restrict__ x2) {
    extern __shared__ float dsf[];
    const int tid = threadIdx.x;
    const int bx = blockIdx.x, by = blockIdx.y;

    if (by < 2) {
        // ------------- linear: v1[n][k] = sum_m x1[n][m]*W[k][m] + b[k] -------------
        float* sX = dsf;                // [32][17]
        float* sW = dsf + 32 * 17;      // [384][17]
        const int L = by * 6 + bx;
        const int n0 = L * 32;
        const int nl = (tid & 15) * 2;
        const int k0 = (tid >> 4) * 24;
        float acc[2][24];
#pragma unroll
        for (int r = 0; r < 2; ++r)
#pragma unroll
            for (int j = 0; j < 24; ++j) acc[r][j] = 0.0f;

        for (int m0 = 0; m0 < N; m0 += 16) {
#pragma unroll
            for (int q = 0; q < 2; ++q) {
                int idx = tid + q * 256;
                int n = idx >> 4, m = idx & 15;
                sX[n * 17 + m] = x1[(size_t)(n0 + n) * N + m0 + m];
            }
#pragma unroll
            for (int q = 0; q < 24; ++q) {
                int idx = tid + q * 256;
                int k = idx >> 4, m = idx & 15;
                sW[k * 17 + m] = W[(size_t)k * N + m0 + m];
            }
            __syncthreads();
#pragma unroll
            for (int mm = 0; mm < 16; ++mm) {
                float x0 = sX[nl * 17 + mm];
                float x1v = sX[(nl + 1) * 17 + mm];
#pragma unroll
                for (int j = 0; j < 24; ++j) {
                    float w = sW[(k0 + j) * 17 + mm];
                    acc[0][j] += x0 * w;
                    acc[1][j] += x1v * w;
                }
            }
            __syncthreads();
        }
#pragma unroll
        for (int r = 0; r < 2; ++r) {
            int n = n0 + nl + r;
            uint32_t* dst = reinterpret_cast<uint32_t*>(g_v1b + (size_t)n * N + k0);
#pragma unroll
            for (int j = 0; j < 12; ++j)
                dst[j] = bf2_pack(acc[r][2 * j] + __ldg(b + k0 + 2 * j),
                                  acc[r][2 * j + 1] + __ldg(b + k0 + 2 * j + 1));
        }
        return;
    }

    // ------------- x2 -> bf16 (direct) + colsum in registers -------------
    const int i = by - 2, s = bx;
    float4* red = reinterpret_cast<float4*>(dsf);   // [192] float4
    if (tid < 192) {
        const int c4 = tid % 96;       // float4 column group
        const int rh = tid / 96;       // row parity
        const float* src = x2 + ((size_t)i * N + s * 64) * N;
        __nv_bfloat16* dst = g_x2b + ((size_t)i * N + s * 64) * N;
        float4 sum = make_float4(0.f, 0.f, 0.f, 0.f);
#pragma unroll
        for (int q = 0; q < 32; ++q) {
            int r = rh + 2 * q;
            float4 f = __ldg(reinterpret_cast<const float4*>(src + (size_t)r * N) + c4);
            sum.x += f.x; sum.y += f.y; sum.z += f.z; sum.w += f.w;
            uint2 u = make_uint2(bf2_pack(f.x, f.y), bf2_pack(f.z, f.w));
            *reinterpret_cast<uint2*>(dst + (size_t)r * N + c4 * 4) = u;
        }
        red[tid] = sum;
    }
    __syncthreads();
    if (tid < 96) {
        float4 a = red[tid], c = red[tid + 96];
        a.x += c.x; a.y += c.y; a.z += c.z; a.w += c.w;
        *reinterpret_cast<float4*>(g_cs6 + ((size_t)i * 6 + s) * N + tid * 4) = a;
    }
}

// ---------------------------------------------------------------------------
// Fused attention: 512 threads, 16 warps = 4 row-groups x 4 col-groups.
// Each warp: 32 rows x 96 cols (2 m-tiles x 12 n8-tiles, 96 acc regs).
// ---------------------------------------------------------------------------
__global__ __launch_bounds__(512, 1)
void attn_kernel(float* __restrict__ out) {
    extern __shared__ char smem[];
    __nv_bfloat16* sQ = reinterpret_cast<__nv_bfloat16*>(smem);
    float* srow = reinterpret_cast<float*>(smem + OFF_SROW);   // [4 wc][128 rows]
    float* cs_s = reinterpret_cast<float*>(smem + OFF_CS);

    const int tid = threadIdx.x;
    const int lane = tid & 31;
    const int warp = tid >> 5;
    const int wr = warp & 3;       // rows wr*32..+32
    const int wc = warp >> 2;      // cols wc*96..+96
    const int i = blockIdx.y;
    const int j0 = blockIdx.x * 128;

    const uint32_t sQu = smem_u32(smem);
    const uint32_t sBu = sQu + OFF_BUF;

    const int rowA = (lane & 7) + ((lane >> 3) & 1) * 8;
    const int colA = (lane >> 4) * 8;
    const uint32_t aBase = sQu + ((wr * 32 + rowA) * QS + colA) * 2;

    const int rowB = (lane & 7) + ((lane >> 4) & 1) * 8;
    const int colB = ((lane >> 3) & 1) * 8;
    const uint32_t bBase1 = sBu + (rowB * BS + colB) * 2;

    const int rowV = (lane & 7) + ((lane >> 3) & 1) * 8;
    const int colV = ((lane >> 4) & 1) * 8;
    const uint32_t bBase2 = sBu + (rowV * VS + colV) * 2;

    // ---- stage Q (contiguous 96KB bf16) + v1 chunks 0,1 ----
    const char* qsrc = reinterpret_cast<const char*>(g_x2b + ((size_t)i * N + j0) * N);
#pragma unroll
    for (int q = 0; q < 12; ++q) {
        int idx = tid + q * 512;           // 6144 transfers of 16B
        int row = idx / 48, c = idx % 48;
        cp16(sQu + row * 784 + c * 16, qsrc + (size_t)idx * 16);
    }
    const char* v1src = reinterpret_cast<const char*>(g_v1b);
#pragma unroll
    for (int q = 0; q < 2; ++q) {          // chunk 0 -> buf0 (768 transfers)
        int idx = tid + q * 512;
        if (idx < 768) {
            int n = idx >> 1, h = idx & 1;
            cp16(sBu + n * 48 + h * 16, v1src + (size_t)n * 768 + h * 16);
        }
    }
    CP_COMMIT();
#pragma unroll
    for (int q = 0; q < 2; ++q) {          // chunk 1 -> buf1
        int idx = tid + q * 512;
        if (idx < 768) {
            int n = idx >> 1, h = idx & 1;
            cp16(sBu + BUF_B + n * 48 + h * 16, v1src + (size_t)n * 768 + 32 + h * 16);
        }
    }
    CP_COMMIT();

    float acc[2][12][4];
#pragma unroll
    for (int ma = 0; ma < 2; ++ma)
#pragma unroll
        for (int na = 0; na < 12; ++na)
#pragma unroll
            for (int r = 0; r < 4; ++r) acc[ma][na][r] = 0.0f;

    // =================== GEMM1: S = Q @ v1^T ===================
    for (int kc = 0; kc < 24; ++kc) {
        const int buf = kc % 3;
        CP_WAIT1();
        __syncthreads();
        if (kc + 2 < 24) {
            const int nb = (kc + 2) % 3;
#pragma unroll
            for (int q = 0; q < 2; ++q) {
                int idx = tid + q * 512;
                if (idx < 768) {
                    int n = idx >> 1, h = idx & 1;
                    cp16(sBu + nb * BUF_B + n * 48 + h * 16,
                         v1src + (size_t)n * 768 + (kc + 2) * 32 + h * 16);
                }
            }
        }
        CP_COMMIT();
        uint32_t a[2][4];
#pragma unroll
        for (int ma = 0; ma < 2; ++ma)
            ldm4(a[ma], aBase + (ma * 16 * QS + kc * 16) * 2);
#pragma unroll
        for (int nbx = 0; nbx < 6; ++nbx) {
            uint32_t bfr[4];
            ldm4(bfr, bBase1 + buf * BUF_B + (wc * 96 + nbx * 16) * 48);
#pragma unroll
            for (int ma = 0; ma < 2; ++ma) {
                mma16816(acc[ma][2 * nbx], a[ma], bfr[0], bfr[1]);
                mma16816(acc[ma][2 * nbx + 1], a[ma], bfr[2], bfr[3]);
            }
        }
    }

    // ---- prefetch V chunks 0,1 (overlap with softmax) ----
    const char* vsrc = reinterpret_cast<const char*>(g_x2b + (size_t)i * N * N);
#pragma unroll
    for (int q = 0; q < 2; ++q) {          // V chunk 0 -> buf0 (768 transfers)
        int idx = tid + q * 512;
        if (idx < 768) {
            int row = idx / 48, c = idx % 48;
            cp16(sBu + row * 784 + c * 16, vsrc + (size_t)idx * 16);
        }
    }
    CP_COMMIT();
#pragma unroll
    for (int q = 0; q < 2; ++q) {          // V chunk 1 -> buf1
        int idx = tid + q * 512;
        if (idx < 768) {
            int row = idx / 48, c = idx % 48;
            cp16(sBu + BUF_B + row * 784 + c * 16, vsrc + 12288 + (size_t)idx * 16);
        }
    }
    CP_COMMIT();

    // ---- colsum -> smem ----
    if (tid < 384) {
        float s0 = 0.f;
#pragma unroll
        for (int p = 0; p < 6; ++p) s0 += __ldg(g_cs6 + ((size_t)i * 6 + p) * N + tid);
        cs_s[tid] = s0;
    }

    // =================== softmax: delta = e/s - 1/N (bf16 into sQ) ===================
    float rs[2][2] = {{0.f, 0.f}, {0.f, 0.f}};
#pragma unroll
    for (int ma = 0; ma < 2; ++ma)
#pragma unroll
        for (int na = 0; na < 12; ++na) {
            float* d = acc[ma][na];
            d[0] = __expf(d[0] * SCALE_INV);
            d[1] = __expf(d[1] * SCALE_INV);
            d[2] = __expf(d[2] * SCALE_INV);
            d[3] = __expf(d[3] * SCALE_INV);
            rs[ma][0] += d[0] + d[1];
            rs[ma][1] += d[2] + d[3];
        }
#pragma unroll
    for (int ma = 0; ma < 2; ++ma)
#pragma unroll
        for (int h = 0; h < 2; ++h) {
            rs[ma][h] += __shfl_xor_sync(0xffffffffu, rs[ma][h], 1);
            rs[ma][h] += __shfl_xor_sync(0xffffffffu, rs[ma][h], 2);
        }
    if ((lane & 3) == 0) {
#pragma unroll
        for (int ma = 0; ma < 2; ++ma)
#pragma unroll
            for (int h = 0; h < 2; ++h)
                srow[wc * 128 + wr * 32 + ma * 16 + h * 8 + (lane >> 2)] = rs[ma][h];
    }
    __syncthreads();
    float invs[2][2];
#pragma unroll
    for (int ma = 0; ma < 2; ++ma)
#pragma unroll
        for (int h = 0; h < 2; ++h) {
            int r = wr * 32 + ma * 16 + h * 8 + (lane >> 2);
            invs[ma][h] = 1.0f / (srow[r] + srow[128 + r] + srow[256 + r] + srow[384 + r]);
        }
#pragma unroll
    for (int ma = 0; ma < 2; ++ma)
#pragma unroll
        for (int na = 0; na < 12; ++na) {
            int r = wr * 32 + ma * 16 + (lane >> 2);
            int c = wc * 96 + (na >> 1) * 16 + (na & 1) * 8 + (lane & 3) * 2;
            float* d = acc[ma][na];
            *reinterpret_cast<uint32_t*>(sQ + r * QS + c) =
                bf2_pack(d[0] * invs[ma][0] - INV_N, d[1] * invs[ma][0] - INV_N);
            *reinterpret_cast<uint32_t*>(sQ + (r + 8) * QS + c) =
                bf2_pack(d[2] * invs[ma][1] - INV_N, d[3] * invs[ma][1] - INV_N);
        }
    __syncthreads();

    // =================== GEMM2: corr = delta @ V ===================
#pragma unroll
    for (int ma = 0; ma < 2; ++ma)
#pragma unroll
        for (int na = 0; na < 12; ++na)
#pragma unroll
            for (int r = 0; r < 4; ++r) acc[ma][na][r] = 0.0f;

    for (int nc = 0; nc < 24; ++nc) {
        const int buf = nc % 3;
        CP_WAIT1();
        __syncthreads();
        if (nc + 2 < 24) {
            const int nb = (nc + 2) % 3;
#pragma unroll
            for (int q = 0; q < 2; ++q) {
                int idx = tid + q * 512;
                if (idx < 768) {
                    int row = idx / 48, c = idx % 48;
                    cp16(sBu + nb * BUF_B + row * 784 + c * 16,
                         vsrc + (size_t)(nc + 2) * 12288 + (size_t)idx * 16);
                }
            }
        }
        CP_COMMIT();
        uint32_t a[2][4];
#pragma unroll
        for (int ma = 0; ma < 2; ++ma)
            ldm4(a[ma], aBase + (ma * 16 * QS + nc * 16) * 2);
#pragma unroll
        for (int nbx = 0; nbx < 6; ++nbx) {
            uint32_t bfr[4];
            ldm4t(bfr, bBase2 + buf * BUF_B + (wc * 96 + nbx * 16) * 2);
#pragma unroll
            for (int ma = 0; ma < 2; ++ma) {
                mma16816(acc[ma][2 * nbx], a[ma], bfr[0], bfr[1]);
                mma16816(acc[ma][2 * nbx + 1], a[ma], bfr[2], bfr[3]);
            }
        }
    }

    // =================== epilogue: out = corr + colsum/384 ===================
#pragma unroll
    for (int ma = 0; ma < 2; ++ma)
#pragma unroll
        for (int nbx = 0; nbx < 6; ++nbx)
#pragma unroll
            for (int ct = 0; ct < 2; ++ct) {
                int na = nbx * 2 + ct;
                int r = j0 + wr * 32 + ma * 16 + (lane >> 2);
                int c = wc * 96 + nbx * 16 + ct * 8 + (lane & 3) * 2;
                float cs0 = cs_s[c] * INV_N;
                float cs1 = cs_s[c + 1] * INV_N;
                float* d = acc[ma][na];
                float2 o0 = make_float2(d[0] + cs0, d[1] + cs1);
                float2 o1 = make_float2(d[2] + cs0, d[3] + cs1);
                *reinterpret_cast<float2*>(out + ((size_t)i * N + r) * N + c) = o0;
                *reinterpret_cast<float2*>(out + ((size_t)i * N + r + 8) * N + c) = o1;
            }
}

// ---------------------------------------------------------------------------
extern "C" void kernel_launch(void* const* d_in, const int* in_sizes, int n_in,
                              void* d_out, int out_size) {
    const float* x1 = (const float*)d_in[0];
    const float* x2 = (const float*)d_in[1];
    const float* W  = (const float*)d_in[2];
    const float* b  = (const float*)d_in[3];
    float* out = (float*)d_out;
    (void)in_sizes; (void)n_in; (void)out_size;

    {
        cudaFuncSetAttribute(prep_kernel, cudaFuncAttributeMaxDynamicSharedMemorySize, SMEM_PREP);
        dim3 g(6, 386);
        prep_kernel<<<g, 256, SMEM_PREP>>>(x1, W, b, x2);
    }
    {
        cudaFuncSetAttribute(attn_kernel, cudaFuncAttributeMaxDynamicSharedMemorySize, SMEM_ATTN);
        dim3 g(3, 384);
        attn_kernel<<<g, 512, SMEM_ATTN>>>(out);
    }
}